// round 16
// baseline (speedup 1.0000x reference)
#include <cuda_runtime.h>
#include <math.h>

// ---------------- static config ----------------
#define B_       2
#define HRV_     32
#define WRV_     1024
#define CRV_     64
#define CB_      256
#define HB_      200
#define WB_      200
#define D_       128
#define HEADS_   8
#define POINTS_  6
#define DH_      16
#define NQ_TOT   65536      // B * HRV * WRV
#define NQ_PERB  32768
#define NV_      40000      // HB*WB
#define PI_F     3.14159265358979323846f

// ---------------- device scratch (static, no cudaMalloc) ----------------
__device__ float g_Wv[CB_ * D_];          // fused pv_w @ vp_w
__device__ float g_bv[D_];
__device__ float g_Wo[D_ * D_];           // fused op_w @ po_w
__device__ float g_bo[D_];
__device__ float g_value[B_ * NV_ * D_];  // [b][n][128]
__device__ float g_Q0[NQ_TOT * D_];
__device__ float g_h1[NQ_TOT * D_];       // range-head stage1 (in-place GN+GELU)
__device__ float g_h2[NQ_TOT * 64];       // conv output
__device__ float g_q1[NQ_TOT * D_];
__device__ float g_query[NQ_TOT * D_];
__device__ float g_offs[NQ_TOT * 96];
__device__ float g_attl[NQ_TOT * 48];
__device__ float g_ref[NQ_TOT * 2];
__device__ float g_sigf[NQ_TOT * 2];
__device__ float g_sincos[NQ_TOT * 2];
__device__ float g_msda[NQ_TOT * D_];
__device__ float g_part[16 * 64 * 2];
__device__ float g_stats[16 * 2];

__device__ __forceinline__ float gelu_exact(float v) {
    return 0.5f * v * (1.0f + erff(v * 0.70710678118654752440f));
}

// ---------------- weight fusion ----------------
__global__ void fuse_weights_kernel(const float* __restrict__ pv_w, const float* __restrict__ pv_b,
                                    const float* __restrict__ vp_w, const float* __restrict__ vp_b,
                                    const float* __restrict__ op_w, const float* __restrict__ op_b,
                                    const float* __restrict__ po_w, const float* __restrict__ po_b) {
    int idx = blockIdx.x * blockDim.x + threadIdx.x;
    if (idx < 32768) {                       // Wv [256][128]
        int i = idx >> 7, j = idx & 127;
        float s = 0.f;
        #pragma unroll 8
        for (int k = 0; k < 128; k++) s = fmaf(pv_w[i * 128 + k], vp_w[k * 128 + j], s);
        g_Wv[idx] = s;
    } else if (idx < 32768 + 128) {          // bv
        int j = idx - 32768;
        float s = vp_b[j];
        for (int k = 0; k < 128; k++) s = fmaf(pv_b[k], vp_w[k * 128 + j], s);
        g_bv[j] = s;
    } else if (idx < 32768 + 128 + 16384) {  // Wo [128][128]
        int e = idx - 32896;
        int i = e >> 7, j = e & 127;
        float s = 0.f;
        #pragma unroll 8
        for (int k = 0; k < 128; k++) s = fmaf(op_w[i * 128 + k], po_w[k * 128 + j], s);
        g_Wo[e] = s;
    } else if (idx < 32768 + 128 + 16384 + 128) {  // bo
        int j = idx - 49280;
        float s = po_b[j];
        for (int k = 0; k < 128; k++) s = fmaf(op_b[k], po_w[k * 128 + j], s);
        g_bo[j] = s;
    }
}

// ---------------- per-token sin/cos of azimuth ----------------
__global__ void sincos_kernel() {
    int t = blockIdx.x * blockDim.x + threadIdx.x;
    if (t >= NQ_TOT) return;
    int w = t & 1023;
    float az = -PI_F + (float)w * (2.0f * PI_F / 1024.0f);
    g_sincos[2 * t]     = sinf(az);
    g_sincos[2 * t + 1] = cosf(az);
}

// ---------------- generic SGEMM: C = A@W (+ Aex@Wex) + bias, optional GELU ----------------
// A row-major [M,K] (lda=K) or, if TRANSA, stored [K,M] with leading dim lda.
// W row-major [K,N]. K must be a multiple of 16.
#define BM 128
#define BN 64
#define BK 16

template <bool TRANSA, bool DOGELU, bool HASEX>
__global__ void __launch_bounds__(256)
sgemm_kernel(const float* __restrict__ A, int lda, long long strideA,
             const float* __restrict__ W, const float* __restrict__ bias,
             const float* __restrict__ Aex, const float* __restrict__ Wex,
             float* __restrict__ C, long long strideC,
             int M, int K, int N) {
    __shared__ float As[BK][BM + 4];
    __shared__ float Ws[BK][BN];
    const float* Ab = A + (long long)blockIdx.z * strideA;
    float* Cb = C + (long long)blockIdx.z * strideC;
    int m0 = blockIdx.y * BM;
    int n0 = blockIdx.x * BN;
    int tid = threadIdx.x;
    int tx = tid & 15, ty = tid >> 4;

    float acc[8][4];
    #pragma unroll
    for (int i = 0; i < 8; i++)
        #pragma unroll
        for (int j = 0; j < 4; j++) acc[i][j] = 0.f;

    for (int k0 = 0; k0 < K; k0 += BK) {
        if (TRANSA) {
            #pragma unroll
            for (int i = tid; i < BK * BM; i += 256) {
                int m = i & (BM - 1), k = i >> 7;   // BM == 128
                int gm = m0 + m;
                As[k][m] = (gm < M) ? Ab[(long long)(k0 + k) * lda + gm] : 0.f;
            }
        } else {
            #pragma unroll
            for (int i = tid; i < BK * BM; i += 256) {
                int k = i & (BK - 1), m = i >> 4;
                int gm = m0 + m;
                As[k][m] = (gm < M) ? Ab[(long long)gm * lda + k0 + k] : 0.f;
            }
        }
        #pragma unroll
        for (int i = tid; i < BK * BN; i += 256) {
            int n = i & (BN - 1), k = i >> 6;
            int gn = n0 + n;
            Ws[k][n] = (gn < N) ? W[(long long)(k0 + k) * N + gn] : 0.f;
        }
        __syncthreads();
        #pragma unroll
        for (int k = 0; k < BK; k++) {
            float a[8], b[4];
            #pragma unroll
            for (int i = 0; i < 8; i++) a[i] = As[k][ty * 8 + i];
            #pragma unroll
            for (int j = 0; j < 4; j++) b[j] = Ws[k][tx * 4 + j];
            #pragma unroll
            for (int i = 0; i < 8; i++)
                #pragma unroll
                for (int j = 0; j < 4; j++) acc[i][j] = fmaf(a[i], b[j], acc[i][j]);
        }
        __syncthreads();
    }

    #pragma unroll
    for (int i = 0; i < 8; i++) {
        int m = m0 + ty * 8 + i;
        if (m >= M) continue;
        float e0 = 0.f, e1 = 0.f;
        if (HASEX) { e0 = Aex[2 * (long long)m]; e1 = Aex[2 * (long long)m + 1]; }
        #pragma unroll
        for (int j = 0; j < 4; j++) {
            int n = n0 + tx * 4 + j;
            if (n >= N) continue;
            float v = acc[i][j] + bias[n];
            if (HASEX) v += e0 * Wex[n] + e1 * Wex[N + n];
            if (DOGELU) v = gelu_exact(v);
            Cb[(long long)m * N + n] = v;
        }
    }
}

// ---------------- 3x3 circular conv (implicit GEMM) ----------------
// in: g_h1 [b,32,1024,128]; w2: [3,3,128,64] HWIO; out: g_h2 [t][64]
__global__ void __launch_bounds__(256)
conv3x3_kernel(const float* __restrict__ x, const float* __restrict__ w2,
               float* __restrict__ y) {
    __shared__ float As[16][68];
    __shared__ float Ws[16][64];
    int t0 = blockIdx.x * 64;
    int b  = t0 >> 15;
    int h  = (t0 >> 10) & 31;
    int w0 = t0 & 1023;
    int tid = threadIdx.x;
    int tx = tid & 15, ty = tid >> 4;

    float acc[4][4];
    #pragma unroll
    for (int i = 0; i < 4; i++)
        #pragma unroll
        for (int j = 0; j < 4; j++) acc[i][j] = 0.f;

    for (int tap = 0; tap < 9; tap++) {
        int dy = tap / 3 - 1, dx = tap % 3 - 1;
        int r = (h + dy) & 31;
        const float* xrow = x + ((long long)(b * 32 + r) * 1024) * 128;
        for (int c0 = 0; c0 < 128; c0 += 16) {
            #pragma unroll
            for (int i = tid; i < 64 * 16; i += 256) {
                int m = i >> 4, k = i & 15;
                int col = (w0 + m + dx) & 1023;
                As[k][m] = xrow[(long long)col * 128 + c0 + k];
            }
            #pragma unroll
            for (int i = tid; i < 16 * 64; i += 256) {
                int n = i & 63, k = i >> 6;
                Ws[k][n] = w2[(tap * 128 + c0 + k) * 64 + n];
            }
            __syncthreads();
            #pragma unroll
            for (int k = 0; k < 16; k++) {
                float a[4], bb[4];
                #pragma unroll
                for (int i = 0; i < 4; i++) a[i] = As[k][ty * 4 + i];
                #pragma unroll
                for (int j = 0; j < 4; j++) bb[j] = Ws[k][tx * 4 + j];
                #pragma unroll
                for (int i = 0; i < 4; i++)
                    #pragma unroll
                    for (int j = 0; j < 4; j++) acc[i][j] = fmaf(a[i], bb[j], acc[i][j]);
            }
            __syncthreads();
        }
    }
    #pragma unroll
    for (int i = 0; i < 4; i++)
        #pragma unroll
        for (int j = 0; j < 4; j++)
            y[(long long)(t0 + ty * 4 + i) * 64 + tx * 4 + j] = acc[i][j];
}

// ---------------- GroupNorm: partial sums ----------------
template <int C, int CPG>
__global__ void gn_partial_kernel(const float* __restrict__ x, float* __restrict__ part) {
    // grid: (64, 16)
    int bg = blockIdx.y;
    int b = bg >> 3, g = bg & 7;
    const float* base = x + ((long long)b * NQ_PERB + blockIdx.x * 512) * C + g * CPG;
    float s = 0.f, s2 = 0.f;
    for (int i = threadIdx.x; i < 512 * CPG; i += 256) {
        int tok = i / CPG, c = i % CPG;
        float v = base[(long long)tok * C + c];
        s += v;
        s2 += v * v;
    }
    __shared__ float sh[256], sh2[256];
    int tid = threadIdx.x;
    sh[tid] = s; sh2[tid] = s2;
    __syncthreads();
    for (int o = 128; o > 0; o >>= 1) {
        if (tid < o) { sh[tid] += sh[tid + o]; sh2[tid] += sh2[tid + o]; }
        __syncthreads();
    }
    if (tid == 0) {
        part[(bg * 64 + blockIdx.x) * 2]     = sh[0];
        part[(bg * 64 + blockIdx.x) * 2 + 1] = sh2[0];
    }
}

__global__ void gn_final_kernel(const float* __restrict__ part, float* __restrict__ stats,
                                float inv_count) {
    int bg = blockIdx.x;
    int tid = threadIdx.x;  // 64
    float s  = part[(bg * 64 + tid) * 2];
    float s2 = part[(bg * 64 + tid) * 2 + 1];
    __shared__ float sh[64], sh2[64];
    sh[tid] = s; sh2[tid] = s2;
    __syncthreads();
    for (int o = 32; o > 0; o >>= 1) {
        if (tid < o) { sh[tid] += sh[tid + o]; sh2[tid] += sh2[tid + o]; }
        __syncthreads();
    }
    if (tid == 0) {
        float mean = sh[0] * inv_count;
        float var  = sh2[0] * inv_count - mean * mean;
        stats[bg * 2]     = mean;
        stats[bg * 2 + 1] = rsqrtf(var + 1e-5f);
    }
}

// ---------------- GN1 apply + GELU (in place, C=128, cpg=16) ----------------
__global__ void gn1_apply_kernel(float* __restrict__ x, const float* __restrict__ gamma,
                                 const float* __restrict__ beta, const float* __restrict__ stats) {
    long long idx = (long long)blockIdx.x * blockDim.x + threadIdx.x;
    if (idx >= (long long)NQ_TOT * 128) return;
    int t = (int)(idx >> 7), c = (int)(idx & 127);
    int bg = (t >> 15) * 8 + (c >> 4);
    float mean = __ldg(&stats[bg * 2]);
    float rstd = __ldg(&stats[bg * 2 + 1]);
    float v = (x[idx] - mean) * rstd * __ldg(&gamma[c]) + __ldg(&beta[c]);
    x[idx] = gelu_exact(v);
}

// ---------------- GN2 apply + GELU + rh_w3 + ref/sigma (fused, per token) ----------------
__global__ void rh_final_kernel(const float* __restrict__ h2,
                                const float* __restrict__ w3, const float* __restrict__ b3,
                                const float* __restrict__ g2, const float* __restrict__ be2,
                                const float* __restrict__ stats) {
    __shared__ float sw[128], sg[64], sb[64];
    int tid = threadIdx.x;
    if (tid < 128) sw[tid] = w3[tid];
    if (tid < 64) { sg[tid] = g2[tid]; sb[tid] = be2[tid]; }
    __syncthreads();
    int t = blockIdx.x * blockDim.x + tid;
    if (t >= NQ_TOT) return;
    int b = t >> 15;
    float mn[8], rs[8];
    #pragma unroll
    for (int g = 0; g < 8; g++) {
        mn[g] = stats[(b * 8 + g) * 2];
        rs[g] = stats[(b * 8 + g) * 2 + 1];
    }
    const float* row = h2 + (long long)t * 64;
    float a0 = 0.f, a1 = 0.f;
    #pragma unroll
    for (int c = 0; c < 64; c++) {
        int g = c >> 3;
        float v = (row[c] - mn[g]) * rs[g] * sg[c] + sb[c];
        v = gelu_exact(v);
        a0 = fmaf(v, sw[c * 2], a0);
        a1 = fmaf(v, sw[c * 2 + 1], a1);
    }
    float mu = fminf(fmaxf(a0 + b3[0], 0.f), 55.f);
    float ls = fminf(fmaxf(a1 + b3[1], -5.f), 3.f);
    float sig = expf(ls);
    int w = t & 1023;
    float az = -PI_F + (float)w * (2.0f * PI_F / 1024.0f);
    float rx = fminf(fmaxf((mu * cosf(az) + 50.f) * 0.01f, 0.f), 1.f);
    float ry = fminf(fmaxf((mu * sinf(az) + 50.f) * 0.01f, 0.f), 1.f);
    g_ref[2 * t]      = rx;
    g_ref[2 * t + 1]  = ry;
    g_sigf[2 * t]     = ls;
    g_sigf[2 * t + 1] = 1.f / (sig + 1e-6f);
}

// ---------------- MSDA sampling ----------------
__global__ void msda_kernel(const float* __restrict__ value,   // [2][40000][128]
                            const float* __restrict__ refb,    // [65536][2]
                            const float* __restrict__ offs,    // [65536][96]
                            const float* __restrict__ attl,    // [65536][48]
                            float* __restrict__ out) {         // [65536][128]
    int idx = blockIdx.x * blockDim.x + threadIdx.x;  // 524288
    int t = idx & 65535;
    int head = idx >> 16;
    int b = t >> 15;
    float rx = refb[2 * t], ry = refb[2 * t + 1];

    const float* lg = attl + (long long)t * 48 + head * 6;
    float l[6];
    float mx = -1e30f;
    #pragma unroll
    for (int p = 0; p < 6; p++) { l[p] = lg[p]; mx = fmaxf(mx, l[p]); }
    float ssum = 0.f;
    #pragma unroll
    for (int p = 0; p < 6; p++) { l[p] = expf(l[p] - mx); ssum += l[p]; }
    float inv = 1.f / ssum;

    const float* op = offs + (long long)t * 96 + head * 12;
    const float* vb = value + (long long)b * NV_ * 128 + head * 16;

    float acc[16];
    #pragma unroll
    for (int q = 0; q < 16; q++) acc[q] = 0.f;

    float bx = rx * 200.f - 0.5f;
    float by = ry * 200.f - 0.5f;
    #pragma unroll
    for (int p = 0; p < 6; p++) {
        float aw = l[p] * inv;
        float px = bx + op[2 * p];
        float py = by + op[2 * p + 1];
        float fx = floorf(px), fy = floorf(py);
        int x0 = (int)fx, y0 = (int)fy;
        float wx = px - fx, wy = py - fy;
        float cw[4] = { (1.f - wx) * (1.f - wy) * aw, wx * (1.f - wy) * aw,
                        (1.f - wx) * wy * aw,        wx * wy * aw };
        int xs[4] = { x0, x0 + 1, x0, x0 + 1 };
        int ys[4] = { y0, y0, y0 + 1, y0 + 1 };
        #pragma unroll
        for (int cnr = 0; cnr < 4; cnr++) {
            int xi = xs[cnr], yi = ys[cnr];
            if (xi >= 0 && xi < 200 && yi >= 0 && yi < 200) {
                const float4* v4 = (const float4*)(vb + (long long)(yi * 200 + xi) * 128);
                float wgt = cw[cnr];
                #pragma unroll
                for (int q = 0; q < 4; q++) {
                    float4 v = __ldg(&v4[q]);
                    acc[4 * q]     = fmaf(wgt, v.x, acc[4 * q]);
                    acc[4 * q + 1] = fmaf(wgt, v.y, acc[4 * q + 1]);
                    acc[4 * q + 2] = fmaf(wgt, v.z, acc[4 * q + 2]);
                    acc[4 * q + 3] = fmaf(wgt, v.w, acc[4 * q + 3]);
                }
            }
        }
    }
    float4* o4 = (float4*)(out + (long long)t * 128 + head * 16);
    #pragma unroll
    for (int q = 0; q < 4; q++)
        o4[q] = make_float4(acc[4 * q], acc[4 * q + 1], acc[4 * q + 2], acc[4 * q + 3]);
}

// ---------------- host launcher ----------------
extern "C" void kernel_launch(void* const* d_in, const int* in_sizes, int n_in,
                              void* d_out, int out_size) {
    const float* x_rv  = (const float*)d_in[0];
    const float* bev   = (const float*)d_in[1];
    const float* pq_w  = (const float*)d_in[2];
    const float* pq_b  = (const float*)d_in[3];
    const float* pv_w  = (const float*)d_in[4];
    const float* pv_b  = (const float*)d_in[5];
    const float* po_w  = (const float*)d_in[6];
    const float* po_b  = (const float*)d_in[7];
    const float* qs_w1 = (const float*)d_in[8];
    const float* qs_b1 = (const float*)d_in[9];
    const float* qs_w2 = (const float*)d_in[10];
    const float* qs_b2 = (const float*)d_in[11];
    const float* rh_w1 = (const float*)d_in[12];
    const float* rh_b1 = (const float*)d_in[13];
    const float* rh_g1 = (const float*)d_in[14];
    const float* rh_be1= (const float*)d_in[15];
    const float* rh_w2 = (const float*)d_in[16];
    const float* rh_g2 = (const float*)d_in[17];
    const float* rh_be2= (const float*)d_in[18];
    const float* rh_w3 = (const float*)d_in[19];
    const float* rh_b3 = (const float*)d_in[20];
    const float* so_w  = (const float*)d_in[21];
    const float* so_b  = (const float*)d_in[22];
    const float* aw_w  = (const float*)d_in[23];
    const float* aw_b  = (const float*)d_in[24];
    const float* vp_w  = (const float*)d_in[25];
    const float* vp_b  = (const float*)d_in[26];
    const float* op_w  = (const float*)d_in[27];
    const float* op_b  = (const float*)d_in[28];
    float* out = (float*)d_out;

    float *p_Wv, *p_bv, *p_Wo, *p_bo, *p_value, *p_Q0, *p_h1, *p_h2, *p_q1, *p_query;
    float *p_offs, *p_attl, *p_ref, *p_sigf, *p_sincos, *p_msda, *p_part, *p_stats;
    cudaGetSymbolAddress((void**)&p_Wv, g_Wv);
    cudaGetSymbolAddress((void**)&p_bv, g_bv);
    cudaGetSymbolAddress((void**)&p_Wo, g_Wo);
    cudaGetSymbolAddress((void**)&p_bo, g_bo);
    cudaGetSymbolAddress((void**)&p_value, g_value);
    cudaGetSymbolAddress((void**)&p_Q0, g_Q0);
    cudaGetSymbolAddress((void**)&p_h1, g_h1);
    cudaGetSymbolAddress((void**)&p_h2, g_h2);
    cudaGetSymbolAddress((void**)&p_q1, g_q1);
    cudaGetSymbolAddress((void**)&p_query, g_query);
    cudaGetSymbolAddress((void**)&p_offs, g_offs);
    cudaGetSymbolAddress((void**)&p_attl, g_attl);
    cudaGetSymbolAddress((void**)&p_ref, g_ref);
    cudaGetSymbolAddress((void**)&p_sigf, g_sigf);
    cudaGetSymbolAddress((void**)&p_sincos, g_sincos);
    cudaGetSymbolAddress((void**)&p_msda, g_msda);
    cudaGetSymbolAddress((void**)&p_part, g_part);
    cudaGetSymbolAddress((void**)&p_stats, g_stats);

    // 1) fused weights
    fuse_weights_kernel<<<(49408 + 255) / 256, 256>>>(pv_w, pv_b, vp_w, vp_b,
                                                      op_w, op_b, po_w, po_b);
    // 2) sin/cos per token
    sincos_kernel<<<NQ_TOT / 256, 256>>>();

    // 3) value = bev^T @ Wv + bv  (per-batch via grid.z)
    {
        dim3 grid((128 + BN - 1) / BN, (NV_ + BM - 1) / BM, 2);
        sgemm_kernel<true, false, false><<<grid, 256>>>(
            bev, NV_, (long long)CB_ * NV_, p_Wv, p_bv, nullptr, nullptr,
            p_value, (long long)NV_ * 128, NV_, CB_, 128);
    }
    // 4) Q0 = x_rv @ pq_w + pq_b
    {
        dim3 grid(2, NQ_TOT / BM, 1);
        sgemm_kernel<false, false, false><<<grid, 256>>>(
            x_rv, CRV_, 0, pq_w, pq_b, nullptr, nullptr, p_Q0, 0, NQ_TOT, CRV_, 128);
    }
    // 5) rh1 = x_rv @ rh_w1[:64] + sincos @ rh_w1[64:66] + rh_b1
    {
        dim3 grid(2, NQ_TOT / BM, 1);
        sgemm_kernel<false, false, true><<<grid, 256>>>(
            x_rv, CRV_, 0, rh_w1, rh_b1, p_sincos, rh_w1 + 64 * 128,
            p_h1, 0, NQ_TOT, CRV_, 128);
    }
    // 6-8) GN1 + GELU (in place)
    gn_partial_kernel<128, 16><<<dim3(64, 16), 256>>>(p_h1, p_part);
    gn_final_kernel<<<16, 64>>>(p_part, p_stats, 1.0f / 524288.0f);
    gn1_apply_kernel<<<(NQ_TOT * 128) / 256, 256>>>(p_h1, rh_g1, rh_be1, p_stats);

    // 9) 3x3 circular conv
    conv3x3_kernel<<<NQ_TOT / 64, 256>>>(p_h1, rh_w2, p_h2);

    // 10-11) GN2 stats
    gn_partial_kernel<64, 8><<<dim3(64, 16), 256>>>(p_h2, p_part);
    gn_final_kernel<<<16, 64>>>(p_part, p_stats, 1.0f / 262144.0f);

    // 12) GN2 apply + GELU + rh_w3 + ref / sig_feat
    rh_final_kernel<<<NQ_TOT / 256, 256>>>(p_h2, rh_w3, rh_b3, rh_g2, rh_be2, p_stats);

    // 13) qs1 (with sig_feat extra rows + GELU)
    {
        dim3 grid(2, NQ_TOT / BM, 1);
        sgemm_kernel<false, true, true><<<grid, 256>>>(
            p_Q0, 128, 0, qs_w1, qs_b1, p_sigf, qs_w1 + 128 * 128,
            p_q1, 0, NQ_TOT, 128, 128);
    }
    // 14) qs2
    {
        dim3 grid(2, NQ_TOT / BM, 1);
        sgemm_kernel<false, false, false><<<grid, 256>>>(
            p_q1, 128, 0, qs_w2, qs_b2, nullptr, nullptr, p_query, 0, NQ_TOT, 128, 128);
    }
    // 15) sampling offsets
    {
        dim3 grid(2, NQ_TOT / BM, 1);  // N=96 -> 2 tiles of 64
        sgemm_kernel<false, false, false><<<grid, 256>>>(
            p_query, 128, 0, so_w, so_b, nullptr, nullptr, p_offs, 0, NQ_TOT, 128, 96);
    }
    // 16) attention logits
    {
        dim3 grid(1, NQ_TOT / BM, 1);  // N=48
        sgemm_kernel<false, false, false><<<grid, 256>>>(
            p_query, 128, 0, aw_w, aw_b, nullptr, nullptr, p_attl, 0, NQ_TOT, 128, 48);
    }
    // 17) MSDA sampling
    msda_kernel<<<(NQ_TOT * HEADS_) / 256, 256>>>(p_value, p_ref, p_offs, p_attl, p_msda);

    // 18) final fused projection -> d_out
    {
        dim3 grid(2, NQ_TOT / BM, 1);
        sgemm_kernel<false, false, false><<<grid, 256>>>(
            p_msda, 128, 0, p_Wo, p_bo, nullptr, nullptr, out, 0, NQ_TOT, 128, 128);
    }
}

// round 17
// speedup vs baseline: 1.0018x; 1.0018x over previous
#include <cuda_runtime.h>
#include <math.h>

// ---------------- static config ----------------
#define B_       2
#define HRV_     32
#define WRV_     1024
#define CRV_     64
#define CB_      256
#define HB_      200
#define WB_      200
#define D_       128
#define HEADS_   8
#define POINTS_  6
#define DH_      16
#define NQ_TOT   65536      // B * HRV * WRV
#define NQ_PERB  32768
#define NV_      40000      // HB*WB
#define PI_F     3.14159265358979323846f

// ---------------- device scratch (static, no cudaMalloc) ----------------
__device__ float g_Wv[CB_ * D_];          // fused pv_w @ vp_w
__device__ float g_bv[D_];
__device__ float g_Wo[D_ * D_];           // fused op_w @ po_w
__device__ float g_bo[D_];
__device__ float g_value[B_ * NV_ * D_];  // [b][n][128]
__device__ float g_Q0[NQ_TOT * D_];
__device__ float g_h1[NQ_TOT * D_];       // range-head stage1 (in-place GN+GELU)
__device__ float g_h2[NQ_TOT * 64];       // conv output
__device__ float g_q1[NQ_TOT * D_];
__device__ float g_query[NQ_TOT * D_];
__device__ float g_offs[NQ_TOT * 96];
__device__ float g_attl[NQ_TOT * 48];
__device__ float g_ref[NQ_TOT * 2];
__device__ float g_sigf[NQ_TOT * 2];
__device__ float g_sincos[NQ_TOT * 2];
__device__ float g_msda[NQ_TOT * D_];
__device__ float g_part[16 * 64 * 2];
__device__ float g_stats[16 * 2];

__device__ __forceinline__ float gelu_exact(float v) {
    return 0.5f * v * (1.0f + erff(v * 0.70710678118654752440f));
}

// ---------------- weight fusion ----------------
__global__ void fuse_weights_kernel(const float* __restrict__ pv_w, const float* __restrict__ pv_b,
                                    const float* __restrict__ vp_w, const float* __restrict__ vp_b,
                                    const float* __restrict__ op_w, const float* __restrict__ op_b,
                                    const float* __restrict__ po_w, const float* __restrict__ po_b) {
    int idx = blockIdx.x * blockDim.x + threadIdx.x;
    if (idx < 32768) {                       // Wv [256][128]
        int i = idx >> 7, j = idx & 127;
        float s = 0.f;
        #pragma unroll 8
        for (int k = 0; k < 128; k++) s = fmaf(pv_w[i * 128 + k], vp_w[k * 128 + j], s);
        g_Wv[idx] = s;
    } else if (idx < 32768 + 128) {          // bv
        int j = idx - 32768;
        float s = vp_b[j];
        for (int k = 0; k < 128; k++) s = fmaf(pv_b[k], vp_w[k * 128 + j], s);
        g_bv[j] = s;
    } else if (idx < 32768 + 128 + 16384) {  // Wo [128][128]
        int e = idx - 32896;
        int i = e >> 7, j = e & 127;
        float s = 0.f;
        #pragma unroll 8
        for (int k = 0; k < 128; k++) s = fmaf(op_w[i * 128 + k], po_w[k * 128 + j], s);
        g_Wo[e] = s;
    } else if (idx < 32768 + 128 + 16384 + 128) {  // bo
        int j = idx - 49280;
        float s = po_b[j];
        for (int k = 0; k < 128; k++) s = fmaf(op_b[k], po_w[k * 128 + j], s);
        g_bo[j] = s;
    }
}

// ---------------- per-token sin/cos of azimuth ----------------
__global__ void sincos_kernel() {
    int t = blockIdx.x * blockDim.x + threadIdx.x;
    if (t >= NQ_TOT) return;
    int w = t & 1023;
    float az = -PI_F + (float)w * (2.0f * PI_F / 1024.0f);
    g_sincos[2 * t]     = sinf(az);
    g_sincos[2 * t + 1] = cosf(az);
}

// ---------------- generic SGEMM: C = A@W (+ Aex@Wex) + bias, optional GELU ----------------
// A row-major [M,K] (lda=K) or, if TRANSA, stored [K,M] with leading dim lda.
// W row-major [K,N]. K must be a multiple of 16.
#define BM 128
#define BN 64
#define BK 16

template <bool TRANSA, bool DOGELU, bool HASEX>
__global__ void __launch_bounds__(256)
sgemm_kernel(const float* __restrict__ A, int lda, long long strideA,
             const float* __restrict__ W, const float* __restrict__ bias,
             const float* __restrict__ Aex, const float* __restrict__ Wex,
             float* __restrict__ C, long long strideC,
             int M, int K, int N) {
    __shared__ float As[BK][BM + 4];
    __shared__ float Ws[BK][BN];
    const float* Ab = A + (long long)blockIdx.z * strideA;
    float* Cb = C + (long long)blockIdx.z * strideC;
    int m0 = blockIdx.y * BM;
    int n0 = blockIdx.x * BN;
    int tid = threadIdx.x;
    int tx = tid & 15, ty = tid >> 4;

    float acc[8][4];
    #pragma unroll
    for (int i = 0; i < 8; i++)
        #pragma unroll
        for (int j = 0; j < 4; j++) acc[i][j] = 0.f;

    for (int k0 = 0; k0 < K; k0 += BK) {
        if (TRANSA) {
            #pragma unroll
            for (int i = tid; i < BK * BM; i += 256) {
                int m = i & (BM - 1), k = i >> 7;   // BM == 128
                int gm = m0 + m;
                As[k][m] = (gm < M) ? Ab[(long long)(k0 + k) * lda + gm] : 0.f;
            }
        } else {
            #pragma unroll
            for (int i = tid; i < BK * BM; i += 256) {
                int k = i & (BK - 1), m = i >> 4;
                int gm = m0 + m;
                As[k][m] = (gm < M) ? Ab[(long long)gm * lda + k0 + k] : 0.f;
            }
        }
        #pragma unroll
        for (int i = tid; i < BK * BN; i += 256) {
            int n = i & (BN - 1), k = i >> 6;
            int gn = n0 + n;
            Ws[k][n] = (gn < N) ? W[(long long)(k0 + k) * N + gn] : 0.f;
        }
        __syncthreads();
        #pragma unroll
        for (int k = 0; k < BK; k++) {
            float a[8], b[4];
            #pragma unroll
            for (int i = 0; i < 8; i++) a[i] = As[k][ty * 8 + i];
            #pragma unroll
            for (int j = 0; j < 4; j++) b[j] = Ws[k][tx * 4 + j];
            #pragma unroll
            for (int i = 0; i < 8; i++)
                #pragma unroll
                for (int j = 0; j < 4; j++) acc[i][j] = fmaf(a[i], b[j], acc[i][j]);
        }
        __syncthreads();
    }

    #pragma unroll
    for (int i = 0; i < 8; i++) {
        int m = m0 + ty * 8 + i;
        if (m >= M) continue;
        float e0 = 0.f, e1 = 0.f;
        if (HASEX) { e0 = Aex[2 * (long long)m]; e1 = Aex[2 * (long long)m + 1]; }
        #pragma unroll
        for (int j = 0; j < 4; j++) {
            int n = n0 + tx * 4 + j;
            if (n >= N) continue;
            float v = acc[i][j] + bias[n];
            if (HASEX) v += e0 * Wex[n] + e1 * Wex[N + n];
            if (DOGELU) v = gelu_exact(v);
            Cb[(long long)m * N + n] = v;
        }
    }
}

// ---------------- 3x3 circular conv (implicit GEMM) ----------------
// in: g_h1 [b,32,1024,128]; w2: [3,3,128,64] HWIO; out: g_h2 [t][64]
__global__ void __launch_bounds__(256)
conv3x3_kernel(const float* __restrict__ x, const float* __restrict__ w2,
               float* __restrict__ y) {
    __shared__ float As[16][68];
    __shared__ float Ws[16][64];
    int t0 = blockIdx.x * 64;
    int b  = t0 >> 15;
    int h  = (t0 >> 10) & 31;
    int w0 = t0 & 1023;
    int tid = threadIdx.x;
    int tx = tid & 15, ty = tid >> 4;

    float acc[4][4];
    #pragma unroll
    for (int i = 0; i < 4; i++)
        #pragma unroll
        for (int j = 0; j < 4; j++) acc[i][j] = 0.f;

    for (int tap = 0; tap < 9; tap++) {
        int dy = tap / 3 - 1, dx = tap % 3 - 1;
        int r = (h + dy) & 31;
        const float* xrow = x + ((long long)(b * 32 + r) * 1024) * 128;
        for (int c0 = 0; c0 < 128; c0 += 16) {
            #pragma unroll
            for (int i = tid; i < 64 * 16; i += 256) {
                int m = i >> 4, k = i & 15;
                int col = (w0 + m + dx) & 1023;
                As[k][m] = xrow[(long long)col * 128 + c0 + k];
            }
            #pragma unroll
            for (int i = tid; i < 16 * 64; i += 256) {
                int n = i & 63, k = i >> 6;
                Ws[k][n] = w2[(tap * 128 + c0 + k) * 64 + n];
            }
            __syncthreads();
            #pragma unroll
            for (int k = 0; k < 16; k++) {
                float a[4], bb[4];
                #pragma unroll
                for (int i = 0; i < 4; i++) a[i] = As[k][ty * 4 + i];
                #pragma unroll
                for (int j = 0; j < 4; j++) bb[j] = Ws[k][tx * 4 + j];
                #pragma unroll
                for (int i = 0; i < 4; i++)
                    #pragma unroll
                    for (int j = 0; j < 4; j++) acc[i][j] = fmaf(a[i], bb[j], acc[i][j]);
            }
            __syncthreads();
        }
    }
    #pragma unroll
    for (int i = 0; i < 4; i++)
        #pragma unroll
        for (int j = 0; j < 4; j++)
            y[(long long)(t0 + ty * 4 + i) * 64 + tx * 4 + j] = acc[i][j];
}

// ---------------- GroupNorm: partial sums ----------------
template <int C, int CPG>
__global__ void gn_partial_kernel(const float* __restrict__ x, float* __restrict__ part) {
    // grid: (64, 16)
    int bg = blockIdx.y;
    int b = bg >> 3, g = bg & 7;
    const float* base = x + ((long long)b * NQ_PERB + blockIdx.x * 512) * C + g * CPG;
    float s = 0.f, s2 = 0.f;
    for (int i = threadIdx.x; i < 512 * CPG; i += 256) {
        int tok = i / CPG, c = i % CPG;
        float v = base[(long long)tok * C + c];
        s += v;
        s2 += v * v;
    }
    __shared__ float sh[256], sh2[256];
    int tid = threadIdx.x;
    sh[tid] = s; sh2[tid] = s2;
    __syncthreads();
    for (int o = 128; o > 0; o >>= 1) {
        if (tid < o) { sh[tid] += sh[tid + o]; sh2[tid] += sh2[tid + o]; }
        __syncthreads();
    }
    if (tid == 0) {
        part[(bg * 64 + blockIdx.x) * 2]     = sh[0];
        part[(bg * 64 + blockIdx.x) * 2 + 1] = sh2[0];
    }
}

__global__ void gn_final_kernel(const float* __restrict__ part, float* __restrict__ stats,
                                float inv_count) {
    int bg = blockIdx.x;
    int tid = threadIdx.x;  // 64
    float s  = part[(bg * 64 + tid) * 2];
    float s2 = part[(bg * 64 + tid) * 2 + 1];
    __shared__ float sh[64], sh2[64];
    sh[tid] = s; sh2[tid] = s2;
    __syncthreads();
    for (int o = 32; o > 0; o >>= 1) {
        if (tid < o) { sh[tid] += sh[tid + o]; sh2[tid] += sh2[tid + o]; }
        __syncthreads();
    }
    if (tid == 0) {
        float mean = sh[0] * inv_count;
        float var  = sh2[0] * inv_count - mean * mean;
        stats[bg * 2]     = mean;
        stats[bg * 2 + 1] = rsqrtf(var + 1e-5f);
    }
}

// ---------------- GN1 apply + GELU (in place, C=128, cpg=16) ----------------
__global__ void gn1_apply_kernel(float* __restrict__ x, const float* __restrict__ gamma,
                                 const float* __restrict__ beta, const float* __restrict__ stats) {
    long long idx = (long long)blockIdx.x * blockDim.x + threadIdx.x;
    if (idx >= (long long)NQ_TOT * 128) return;
    int t = (int)(idx >> 7), c = (int)(idx & 127);
    int bg = (t >> 15) * 8 + (c >> 4);
    float mean = __ldg(&stats[bg * 2]);
    float rstd = __ldg(&stats[bg * 2 + 1]);
    float v = (x[idx] - mean) * rstd * __ldg(&gamma[c]) + __ldg(&beta[c]);
    x[idx] = gelu_exact(v);
}

// ---------------- GN2 apply + GELU + rh_w3 + ref/sigma (fused, per token) ----------------
__global__ void rh_final_kernel(const float* __restrict__ h2,
                                const float* __restrict__ w3, const float* __restrict__ b3,
                                const float* __restrict__ g2, const float* __restrict__ be2,
                                const float* __restrict__ stats) {
    __shared__ float sw[128], sg[64], sb[64];
    int tid = threadIdx.x;
    if (tid < 128) sw[tid] = w3[tid];
    if (tid < 64) { sg[tid] = g2[tid]; sb[tid] = be2[tid]; }
    __syncthreads();
    int t = blockIdx.x * blockDim.x + tid;
    if (t >= NQ_TOT) return;
    int b = t >> 15;
    float mn[8], rs[8];
    #pragma unroll
    for (int g = 0; g < 8; g++) {
        mn[g] = stats[(b * 8 + g) * 2];
        rs[g] = stats[(b * 8 + g) * 2 + 1];
    }
    const float* row = h2 + (long long)t * 64;
    float a0 = 0.f, a1 = 0.f;
    #pragma unroll
    for (int c = 0; c < 64; c++) {
        int g = c >> 3;
        float v = (row[c] - mn[g]) * rs[g] * sg[c] + sb[c];
        v = gelu_exact(v);
        a0 = fmaf(v, sw[c * 2], a0);
        a1 = fmaf(v, sw[c * 2 + 1], a1);
    }
    float mu = fminf(fmaxf(a0 + b3[0], 0.f), 55.f);
    float ls = fminf(fmaxf(a1 + b3[1], -5.f), 3.f);
    float sig = expf(ls);
    int w = t & 1023;
    float az = -PI_F + (float)w * (2.0f * PI_F / 1024.0f);
    float rx = fminf(fmaxf((mu * cosf(az) + 50.f) * 0.01f, 0.f), 1.f);
    float ry = fminf(fmaxf((mu * sinf(az) + 50.f) * 0.01f, 0.f), 1.f);
    g_ref[2 * t]      = rx;
    g_ref[2 * t + 1]  = ry;
    g_sigf[2 * t]     = ls;
    g_sigf[2 * t + 1] = 1.f / (sig + 1e-6f);
}

// ---------------- MSDA sampling ----------------
__global__ void msda_kernel(const float* __restrict__ value,   // [2][40000][128]
                            const float* __restrict__ refb,    // [65536][2]
                            const float* __restrict__ offs,    // [65536][96]
                            const float* __restrict__ attl,    // [65536][48]
                            float* __restrict__ out) {         // [65536][128]
    int idx = blockIdx.x * blockDim.x + threadIdx.x;  // 524288
    int t = idx & 65535;
    int head = idx >> 16;
    int b = t >> 15;
    float rx = refb[2 * t], ry = refb[2 * t + 1];

    const float* lg = attl + (long long)t * 48 + head * 6;
    float l[6];
    float mx = -1e30f;
    #pragma unroll
    for (int p = 0; p < 6; p++) { l[p] = lg[p]; mx = fmaxf(mx, l[p]); }
    float ssum = 0.f;
    #pragma unroll
    for (int p = 0; p < 6; p++) { l[p] = expf(l[p] - mx); ssum += l[p]; }
    float inv = 1.f / ssum;

    const float* op = offs + (long long)t * 96 + head * 12;
    const float* vb = value + (long long)b * NV_ * 128 + head * 16;

    float acc[16];
    #pragma unroll
    for (int q = 0; q < 16; q++) acc[q] = 0.f;

    float bx = rx * 200.f - 0.5f;
    float by = ry * 200.f - 0.5f;
    #pragma unroll
    for (int p = 0; p < 6; p++) {
        float aw = l[p] * inv;
        float px = bx + op[2 * p];
        float py = by + op[2 * p + 1];
        float fx = floorf(px), fy = floorf(py);
        int x0 = (int)fx, y0 = (int)fy;
        float wx = px - fx, wy = py - fy;
        float cw[4] = { (1.f - wx) * (1.f - wy) * aw, wx * (1.f - wy) * aw,
                        (1.f - wx) * wy * aw,        wx * wy * aw };
        int xs[4] = { x0, x0 + 1, x0, x0 + 1 };
        int ys[4] = { y0, y0, y0 + 1, y0 + 1 };
        #pragma unroll
        for (int cnr = 0; cnr < 4; cnr++) {
            int xi = xs[cnr], yi = ys[cnr];
            if (xi >= 0 && xi < 200 && yi >= 0 && yi < 200) {
                const float4* v4 = (const float4*)(vb + (long long)(yi * 200 + xi) * 128);
                float wgt = cw[cnr];
                #pragma unroll
                for (int q = 0; q < 4; q++) {
                    float4 v = __ldg(&v4[q]);
                    acc[4 * q]     = fmaf(wgt, v.x, acc[4 * q]);
                    acc[4 * q + 1] = fmaf(wgt, v.y, acc[4 * q + 1]);
                    acc[4 * q + 2] = fmaf(wgt, v.z, acc[4 * q + 2]);
                    acc[4 * q + 3] = fmaf(wgt, v.w, acc[4 * q + 3]);
                }
            }
        }
    }
    float4* o4 = (float4*)(out + (long long)t * 128 + head * 16);
    #pragma unroll
    for (int q = 0; q < 4; q++)
        o4[q] = make_float4(acc[4 * q], acc[4 * q + 1], acc[4 * q + 2], acc[4 * q + 3]);
}

// ---------------- host launcher ----------------
extern "C" void kernel_launch(void* const* d_in, const int* in_sizes, int n_in,
                              void* d_out, int out_size) {
    const float* x_rv  = (const float*)d_in[0];
    const float* bev   = (const float*)d_in[1];
    const float* pq_w  = (const float*)d_in[2];
    const float* pq_b  = (const float*)d_in[3];
    const float* pv_w  = (const float*)d_in[4];
    const float* pv_b  = (const float*)d_in[5];
    const float* po_w  = (const float*)d_in[6];
    const float* po_b  = (const float*)d_in[7];
    const float* qs_w1 = (const float*)d_in[8];
    const float* qs_b1 = (const float*)d_in[9];
    const float* qs_w2 = (const float*)d_in[10];
    const float* qs_b2 = (const float*)d_in[11];
    const float* rh_w1 = (const float*)d_in[12];
    const float* rh_b1 = (const float*)d_in[13];
    const float* rh_g1 = (const float*)d_in[14];
    const float* rh_be1= (const float*)d_in[15];
    const float* rh_w2 = (const float*)d_in[16];
    const float* rh_g2 = (const float*)d_in[17];
    const float* rh_be2= (const float*)d_in[18];
    const float* rh_w3 = (const float*)d_in[19];
    const float* rh_b3 = (const float*)d_in[20];
    const float* so_w  = (const float*)d_in[21];
    const float* so_b  = (const float*)d_in[22];
    const float* aw_w  = (const float*)d_in[23];
    const float* aw_b  = (const float*)d_in[24];
    const float* vp_w  = (const float*)d_in[25];
    const float* vp_b  = (const float*)d_in[26];
    const float* op_w  = (const float*)d_in[27];
    const float* op_b  = (const float*)d_in[28];
    float* out = (float*)d_out;

    float *p_Wv, *p_bv, *p_Wo, *p_bo, *p_value, *p_Q0, *p_h1, *p_h2, *p_q1, *p_query;
    float *p_offs, *p_attl, *p_ref, *p_sigf, *p_sincos, *p_msda, *p_part, *p_stats;
    cudaGetSymbolAddress((void**)&p_Wv, g_Wv);
    cudaGetSymbolAddress((void**)&p_bv, g_bv);
    cudaGetSymbolAddress((void**)&p_Wo, g_Wo);
    cudaGetSymbolAddress((void**)&p_bo, g_bo);
    cudaGetSymbolAddress((void**)&p_value, g_value);
    cudaGetSymbolAddress((void**)&p_Q0, g_Q0);
    cudaGetSymbolAddress((void**)&p_h1, g_h1);
    cudaGetSymbolAddress((void**)&p_h2, g_h2);
    cudaGetSymbolAddress((void**)&p_q1, g_q1);
    cudaGetSymbolAddress((void**)&p_query, g_query);
    cudaGetSymbolAddress((void**)&p_offs, g_offs);
    cudaGetSymbolAddress((void**)&p_attl, g_attl);
    cudaGetSymbolAddress((void**)&p_ref, g_ref);
    cudaGetSymbolAddress((void**)&p_sigf, g_sigf);
    cudaGetSymbolAddress((void**)&p_sincos, g_sincos);
    cudaGetSymbolAddress((void**)&p_msda, g_msda);
    cudaGetSymbolAddress((void**)&p_part, g_part);
    cudaGetSymbolAddress((void**)&p_stats, g_stats);

    // 1) fused weights
    fuse_weights_kernel<<<(49408 + 255) / 256, 256>>>(pv_w, pv_b, vp_w, vp_b,
                                                      op_w, op_b, po_w, po_b);
    // 2) sin/cos per token
    sincos_kernel<<<NQ_TOT / 256, 256>>>();

    // 3) value = bev^T @ Wv + bv  (per-batch via grid.z)
    {
        dim3 grid((128 + BN - 1) / BN, (NV_ + BM - 1) / BM, 2);
        sgemm_kernel<true, false, false><<<grid, 256>>>(
            bev, NV_, (long long)CB_ * NV_, p_Wv, p_bv, nullptr, nullptr,
            p_value, (long long)NV_ * 128, NV_, CB_, 128);
    }
    // 4) Q0 = x_rv @ pq_w + pq_b
    {
        dim3 grid(2, NQ_TOT / BM, 1);
        sgemm_kernel<false, false, false><<<grid, 256>>>(
            x_rv, CRV_, 0, pq_w, pq_b, nullptr, nullptr, p_Q0, 0, NQ_TOT, CRV_, 128);
    }
    // 5) rh1 = x_rv @ rh_w1[:64] + sincos @ rh_w1[64:66] + rh_b1
    {
        dim3 grid(2, NQ_TOT / BM, 1);
        sgemm_kernel<false, false, true><<<grid, 256>>>(
            x_rv, CRV_, 0, rh_w1, rh_b1, p_sincos, rh_w1 + 64 * 128,
            p_h1, 0, NQ_TOT, CRV_, 128);
    }
    // 6-8) GN1 + GELU (in place)
    gn_partial_kernel<128, 16><<<dim3(64, 16), 256>>>(p_h1, p_part);
    gn_final_kernel<<<16, 64>>>(p_part, p_stats, 1.0f / 524288.0f);
    gn1_apply_kernel<<<(NQ_TOT * 128) / 256, 256>>>(p_h1, rh_g1, rh_be1, p_stats);

    // 9) 3x3 circular conv
    conv3x3_kernel<<<NQ_TOT / 64, 256>>>(p_h1, rh_w2, p_h2);

    // 10-11) GN2 stats
    gn_partial_kernel<64, 8><<<dim3(64, 16), 256>>>(p_h2, p_part);
    gn_final_kernel<<<16, 64>>>(p_part, p_stats, 1.0f / 262144.0f);

    // 12) GN2 apply + GELU + rh_w3 + ref / sig_feat
    rh_final_kernel<<<NQ_TOT / 256, 256>>>(p_h2, rh_w3, rh_b3, rh_g2, rh_be2, p_stats);

    // 13) qs1 (with sig_feat extra rows + GELU)
    {
        dim3 grid(2, NQ_TOT / BM, 1);
        sgemm_kernel<false, true, true><<<grid, 256>>>(
            p_Q0, 128, 0, qs_w1, qs_b1, p_sigf, qs_w1 + 128 * 128,
            p_q1, 0, NQ_TOT, 128, 128);
    }
    // 14) qs2
    {
        dim3 grid(2, NQ_TOT / BM, 1);
        sgemm_kernel<false, false, false><<<grid, 256>>>(
            p_q1, 128, 0, qs_w2, qs_b2, nullptr, nullptr, p_query, 0, NQ_TOT, 128, 128);
    }
    // 15) sampling offsets
    {
        dim3 grid(2, NQ_TOT / BM, 1);  // N=96 -> 2 tiles of 64
        sgemm_kernel<false, false, false><<<grid, 256>>>(
            p_query, 128, 0, so_w, so_b, nullptr, nullptr, p_offs, 0, NQ_TOT, 128, 96);
    }
    // 16) attention logits
    {
        dim3 grid(1, NQ_TOT / BM, 1);  // N=48
        sgemm_kernel<false, false, false><<<grid, 256>>>(
            p_query, 128, 0, aw_w, aw_b, nullptr, nullptr, p_attl, 0, NQ_TOT, 128, 48);
    }
    // 17) MSDA sampling
    msda_kernel<<<(NQ_TOT * HEADS_) / 256, 256>>>(p_value, p_ref, p_offs, p_attl, p_msda);

    // 18) final fused projection -> d_out
    {
        dim3 grid(2, NQ_TOT / BM, 1);
        sgemm_kernel<false, false, false><<<grid, 256>>>(
            p_msda, 128, 0, p_Wo, p_bo, nullptr, nullptr, out, 0, NQ_TOT, 128, 128);
    }
}